// round 4
// baseline (speedup 1.0000x reference)
#include <cuda_runtime.h>
#include <cstdint>

#define BB 16
#define LL 2048
#define DD 128
#define NROW (BB * LL)

__device__ unsigned g_rmax_enc[NROW];
__device__ unsigned g_cmax_enc[NROW];
__device__ float    g_rowsum[NROW];
__device__ float    g_colsum[NROW];
__device__ float    g_rmax[NROW];
__device__ float    g_E[NROW];
__device__ float    g_rfac[NROW];
__device__ float    g_cfac[NROW];

__device__ __forceinline__ unsigned fenc(float f) {
    unsigned u = __float_as_uint(f);
    return (u & 0x80000000u) ? ~u : (u | 0x80000000u);
}
__device__ __forceinline__ float fdec(unsigned u) {
    return (u & 0x80000000u) ? __uint_as_float(u & 0x7fffffffu) : __uint_as_float(~u);
}

// FMA-only exp (MUFU rt=8 is too slow for 67M elements). ~1e-7 rel err.
__device__ __forceinline__ float fexp(float x) {
    float y = x * 1.4426950408889634f;
    y = fminf(fmaxf(y, -126.0f), 126.0f);
    float t = y + 12582912.0f;
    int   n = __float_as_int(t) - 0x4B400000;
    float f = y - (t - 12582912.0f);
    float p = fmaf(1.5403530e-4f, f, 1.3333558e-3f);
    p = fmaf(p, f, 9.6181291e-3f);
    p = fmaf(p, f, 5.5504109e-2f);
    p = fmaf(p, f, 2.4022651e-1f);
    p = fmaf(p, f, 6.9314718e-1f);
    p = fmaf(p, f, 1.0f);
    return p * __int_as_float((n + 127) << 23);
}

__device__ __forceinline__ unsigned long long pk2(float lo, float hi) {
    unsigned long long r;
    asm("mov.b64 %0, {%1,%2};" : "=l"(r) : "f"(lo), "f"(hi));
    return r;
}
__device__ __forceinline__ void upk2(float& lo, float& hi, unsigned long long v) {
    asm("mov.b64 {%0,%1}, %2;" : "=f"(lo), "=f"(hi) : "l"(v));
}
__device__ __forceinline__ unsigned long long ffma2(unsigned long long a,
                                                    unsigned long long b,
                                                    unsigned long long c) {
    unsigned long long d;
    asm("fma.rn.f32x2 %0, %1, %2, %3;" : "=l"(d) : "l"(a), "l"(b), "l"(c));
    return d;
}

__global__ void k_init() {
    int i = blockIdx.x * blockDim.x + threadIdx.x;
    if (i < NROW) {
        g_rmax_enc[i] = 0u; g_cmax_enc[i] = 0u;
        g_rowsum[i] = 0.0f; g_colsum[i] = 0.0f;
    }
}

// attn = q @ k^T (f32x2), fused tile-local row/col max -> global atomicMax
__global__ __launch_bounds__(256, 1)
void k_gemm_qk(const float* __restrict__ q, const float* __restrict__ kmat,
               float* __restrict__ attn)
{
    __shared__ float As[32][132];
    __shared__ float Bs[32][132];
    __shared__ unsigned s_rm[128];
    __shared__ unsigned s_cm[128];

    const int tid = threadIdx.x;
    const int tx = tid & 15, ty = tid >> 4;
    const int b  = blockIdx.z;
    const int m0 = blockIdx.y * 128;
    const int n0 = blockIdx.x * 128;
    const float* qb = q    + (size_t)b * LL * DD;
    const float* kb = kmat + (size_t)b * LL * DD;

    if (tid < 128) { s_rm[tid] = 0u; s_cm[tid] = 0u; }

    unsigned long long acc[8][4];
#pragma unroll
    for (int i = 0; i < 8; i++)
#pragma unroll
        for (int j = 0; j < 4; j++) acc[i][j] = 0ULL;

    for (int kc = 0; kc < DD; kc += 32) {
#pragma unroll
        for (int p = 0; p < 4; p++) {
            int idx = tid + p * 256;
            int r = idx >> 3, c = idx & 7;
            float4 vq = *reinterpret_cast<const float4*>(qb + (size_t)(m0 + r) * DD + kc + 4 * c);
            As[4*c+0][r] = vq.x; As[4*c+1][r] = vq.y; As[4*c+2][r] = vq.z; As[4*c+3][r] = vq.w;
            float4 vk = *reinterpret_cast<const float4*>(kb + (size_t)(n0 + r) * DD + kc + 4 * c);
            Bs[4*c+0][r] = vk.x; Bs[4*c+1][r] = vk.y; Bs[4*c+2][r] = vk.z; Bs[4*c+3][r] = vk.w;
        }
        __syncthreads();
#pragma unroll 8
        for (int s = 0; s < 32; s++) {
            float4 a0 = *reinterpret_cast<const float4*>(&As[s][ty * 8]);
            float4 a1 = *reinterpret_cast<const float4*>(&As[s][ty * 8 + 4]);
            ulonglong2 b0 = *reinterpret_cast<const ulonglong2*>(&Bs[s][tx * 8]);
            ulonglong2 b1 = *reinterpret_cast<const ulonglong2*>(&Bs[s][tx * 8 + 4]);
            unsigned long long ad[8];
            ad[0] = pk2(a0.x, a0.x); ad[1] = pk2(a0.y, a0.y);
            ad[2] = pk2(a0.z, a0.z); ad[3] = pk2(a0.w, a0.w);
            ad[4] = pk2(a1.x, a1.x); ad[5] = pk2(a1.y, a1.y);
            ad[6] = pk2(a1.z, a1.z); ad[7] = pk2(a1.w, a1.w);
#pragma unroll
            for (int i = 0; i < 8; i++) {
                acc[i][0] = ffma2(ad[i], b0.x, acc[i][0]);
                acc[i][1] = ffma2(ad[i], b0.y, acc[i][1]);
                acc[i][2] = ffma2(ad[i], b1.x, acc[i][2]);
                acc[i][3] = ffma2(ad[i], b1.y, acc[i][3]);
            }
        }
        __syncthreads();
    }

    float cm[8];
#pragma unroll
    for (int j = 0; j < 8; j++) cm[j] = -3.4e38f;
#pragma unroll
    for (int i = 0; i < 8; i++) {
        float v0,v1,v2,v3,v4,v5,v6,v7;
        upk2(v0, v1, acc[i][0]); upk2(v2, v3, acc[i][1]);
        upk2(v4, v5, acc[i][2]); upk2(v6, v7, acc[i][3]);
        float rm = fmaxf(fmaxf(fmaxf(v0, v1), fmaxf(v2, v3)),
                         fmaxf(fmaxf(v4, v5), fmaxf(v6, v7)));
        atomicMax(&s_rm[ty * 8 + i], fenc(rm));
        cm[0]=fmaxf(cm[0],v0); cm[1]=fmaxf(cm[1],v1); cm[2]=fmaxf(cm[2],v2); cm[3]=fmaxf(cm[3],v3);
        cm[4]=fmaxf(cm[4],v4); cm[5]=fmaxf(cm[5],v5); cm[6]=fmaxf(cm[6],v6); cm[7]=fmaxf(cm[7],v7);
        float* o = attn + ((size_t)(b * LL + m0 + ty * 8 + i)) * LL + n0 + tx * 8;
        *reinterpret_cast<float4*>(o)     = make_float4(v0, v1, v2, v3);
        *reinterpret_cast<float4*>(o + 4) = make_float4(v4, v5, v6, v7);
    }
#pragma unroll
    for (int j = 0; j < 8; j++) atomicMax(&s_cm[tx * 8 + j], fenc(cm[j]));
    __syncthreads();
    if (tid < 128) {
        atomicMax(&g_rmax_enc[b * LL + m0 + tid], s_rm[tid]);
        atomicMax(&g_cmax_enc[b * LL + n0 + tid], s_cm[tid]);
    }
}

__global__ void k_prep() {
    int i = blockIdx.x * blockDim.x + threadIdx.x;
    if (i < NROW) {
        float rm = fdec(g_rmax_enc[i]);
        g_rmax[i] = rm;
        g_E[i] = fexp(rm);
        g_cfac[i] = fexp(-fdec(g_cmax_enc[i]));  // stage C_j here temporarily
    }
}

// er = exp(a - rmax_i)*m in place; rowsum_i += er; colsum_raw_j += er*E_i
__global__ __launch_bounds__(256)
void k_pass(float* __restrict__ buf, const float* __restrict__ mask)
{
    __shared__ float s_rs[128];
    __shared__ float s_rmax[128];
    __shared__ float s_E[128];
    const int tid = threadIdx.x;
    const int b  = blockIdx.z;
    const int r0 = blockIdx.y * 128;
    const int c0 = blockIdx.x * 128;
    if (tid < 128) {
        s_rs[tid] = 0.0f;
        s_rmax[tid] = g_rmax[b * LL + r0 + tid];
        s_E[tid]    = g_E[b * LL + r0 + tid];
    }
    __syncthreads();
    const int c = tid & 127;
    const int half = tid >> 7;
    const int lane = tid & 31;
    float csum = 0.0f;
    size_t base = ((size_t)(b * LL + r0)) * LL + c0;
    for (int r = half; r < 128; r += 2) {
        size_t idx = base + (size_t)r * LL + c;
        float er = fexp(buf[idx] - s_rmax[r]) * mask[idx];
        buf[idx] = er;
        csum = fmaf(er, s_E[r], csum);
        float w = er;
        w += __shfl_xor_sync(0xffffffffu, w, 16);
        w += __shfl_xor_sync(0xffffffffu, w, 8);
        w += __shfl_xor_sync(0xffffffffu, w, 4);
        w += __shfl_xor_sync(0xffffffffu, w, 2);
        w += __shfl_xor_sync(0xffffffffu, w, 1);
        if (lane == 0) atomicAdd(&s_rs[r], w);
    }
    atomicAdd(&g_colsum[b * LL + c0 + c], csum);
    __syncthreads();
    if (tid < 128) atomicAdd(&g_rowsum[b * LL + r0 + tid], s_rs[tid]);
}

__global__ void k_facts() {
    int i = blockIdx.x * blockDim.x + threadIdx.x;
    if (i < NROW) {
        g_rfac[i] = g_E[i] / (g_rowsum[i] + 1e-12f);
        float C = g_cfac[i];                       // staged C_j
        g_cfac[i] = C / (g_colsum[i] * C + 1e-12f);
    }
}

// gated = er^2 * rfac_i * cfac_j (in place)
__global__ __launch_bounds__(256)
void k_gate(float* __restrict__ buf)
{
    int e4  = blockIdx.x * 256 + threadIdx.x;
    int row = e4 >> 9;
    int b   = row >> 11;
    int col = (e4 & 511) << 2;
    float rf = g_rfac[row];
    float4 cf = *reinterpret_cast<const float4*>(&g_cfac[(b << 11) + col]);
    float4 e = reinterpret_cast<float4*>(buf)[e4];
    e.x = e.x * e.x * rf * cf.x;
    e.y = e.y * e.y * rf * cf.y;
    e.z = e.z * e.z * rf * cf.z;
    e.w = e.w * e.w * rf * cf.w;
    reinterpret_cast<float4*>(buf)[e4] = e;
}

// out = gated @ v (f32x2)
__global__ __launch_bounds__(256, 1)
void k_gemm_pv(const float* __restrict__ gated, const float* __restrict__ v,
               float* __restrict__ out)
{
    __shared__ float Gs[32][132];
    __shared__ float Vs[32][132];
    const int tid = threadIdx.x;
    const int tx = tid & 15, ty = tid >> 4;
    const int b  = blockIdx.y;
    const int m0 = blockIdx.x * 128;
    const float* gb = gated + (size_t)b * LL * LL;
    const float* vb = v     + (size_t)b * LL * DD;

    unsigned long long acc[8][4];
#pragma unroll
    for (int i = 0; i < 8; i++)
#pragma unroll
        for (int j = 0; j < 4; j++) acc[i][j] = 0ULL;

    for (int k0 = 0; k0 < LL; k0 += 32) {
#pragma unroll
        for (int p = 0; p < 4; p++) {
            int idx = tid + p * 256;
            int r = idx >> 3, c = idx & 7;
            float4 vg = *reinterpret_cast<const float4*>(gb + (size_t)(m0 + r) * LL + k0 + 4 * c);
            Gs[4*c+0][r] = vg.x; Gs[4*c+1][r] = vg.y; Gs[4*c+2][r] = vg.z; Gs[4*c+3][r] = vg.w;
            int kr = idx >> 5, cc = idx & 31;
            *reinterpret_cast<float4*>(&Vs[kr][4 * cc]) =
                *reinterpret_cast<const float4*>(vb + (size_t)(k0 + kr) * DD + 4 * cc);
        }
        __syncthreads();
#pragma unroll 8
        for (int s = 0; s < 32; s++) {
            float4 a0 = *reinterpret_cast<const float4*>(&Gs[s][ty * 8]);
            float4 a1 = *reinterpret_cast<const float4*>(&Gs[s][ty * 8 + 4]);
            ulonglong2 b0 = *reinterpret_cast<const ulonglong2*>(&Vs[s][tx * 8]);
            ulonglong2 b1 = *reinterpret_cast<const ulonglong2*>(&Vs[s][tx * 8 + 4]);
            unsigned long long ad[8];
            ad[0] = pk2(a0.x, a0.x); ad[1] = pk2(a0.y, a0.y);
            ad[2] = pk2(a0.z, a0.z); ad[3] = pk2(a0.w, a0.w);
            ad[4] = pk2(a1.x, a1.x); ad[5] = pk2(a1.y, a1.y);
            ad[6] = pk2(a1.z, a1.z); ad[7] = pk2(a1.w, a1.w);
#pragma unroll
            for (int i = 0; i < 8; i++) {
                acc[i][0] = ffma2(ad[i], b0.x, acc[i][0]);
                acc[i][1] = ffma2(ad[i], b0.y, acc[i][1]);
                acc[i][2] = ffma2(ad[i], b1.x, acc[i][2]);
                acc[i][3] = ffma2(ad[i], b1.y, acc[i][3]);
            }
        }
        __syncthreads();
    }
#pragma unroll
    for (int i = 0; i < 8; i++) {
        float v0,v1,v2,v3,v4,v5,v6,v7;
        upk2(v0, v1, acc[i][0]); upk2(v2, v3, acc[i][1]);
        upk2(v4, v5, acc[i][2]); upk2(v6, v7, acc[i][3]);
        float* o = out + ((size_t)(b * LL + m0 + ty * 8 + i)) * DD + tx * 8;
        *reinterpret_cast<float4*>(o)     = make_float4(v0, v1, v2, v3);
        *reinterpret_cast<float4*>(o + 4) = make_float4(v4, v5, v6, v7);
    }
}

extern "C" void kernel_launch(void* const* d_in, const int* in_sizes, int n_in,
                              void* d_out, int out_size)
{
    (void)in_sizes; (void)n_in; (void)out_size;
    const float* q    = (const float*)d_in[0];
    const float* k    = (const float*)d_in[1];
    const float* v    = (const float*)d_in[2];
    const float* mask = (const float*)d_in[3];
    float* out   = (float*)d_out;
    float* gated = out + (size_t)BB * LL * DD;   // scratch = gated output region

    k_init<<<NROW / 256, 256>>>();
    k_gemm_qk<<<dim3(16, 16, 16), 256>>>(q, k, gated);
    k_prep<<<NROW / 256, 256>>>();
    k_pass<<<dim3(16, 16, 16), 256>>>(gated, mask);
    k_facts<<<NROW / 256, 256>>>();
    k_gate<<<(int)(((size_t)BB * LL * LL / 4) / 256), 256>>>(gated);
    k_gemm_pv<<<dim3(16, 16), 256>>>(gated, v, out);
}

// round 6
// speedup vs baseline: 1.0007x; 1.0007x over previous
#include <cuda_runtime.h>
#include <cstdint>

#define BB 16
#define LL 2048
#define DD 128
#define NROW (BB * LL)

__device__ unsigned g_rmax_enc[NROW];
__device__ unsigned g_cmax_enc[NROW];
__device__ float    g_rowsum[NROW];
__device__ float    g_colsum[NROW];
__device__ float    g_rmax[NROW];
__device__ float    g_E[NROW];
__device__ float    g_rfac[NROW];
__device__ float    g_cfac[NROW];

__device__ __forceinline__ unsigned fenc(float f) {
    unsigned u = __float_as_uint(f);
    return (u & 0x80000000u) ? ~u : (u | 0x80000000u);
}
__device__ __forceinline__ float fdec(unsigned u) {
    return (u & 0x80000000u) ? __uint_as_float(u & 0x7fffffffu) : __uint_as_float(~u);
}

// FMA-only exp (MUFU rt=8 is too slow for 67M elements). ~1e-7 rel err.
__device__ __forceinline__ float fexp(float x) {
    float y = x * 1.4426950408889634f;
    y = fminf(fmaxf(y, -126.0f), 126.0f);
    float t = y + 12582912.0f;
    int   n = __float_as_int(t) - 0x4B400000;
    float f = y - (t - 12582912.0f);
    float p = fmaf(1.5403530e-4f, f, 1.3333558e-3f);
    p = fmaf(p, f, 9.6181291e-3f);
    p = fmaf(p, f, 5.5504109e-2f);
    p = fmaf(p, f, 2.4022651e-1f);
    p = fmaf(p, f, 6.9314718e-1f);
    p = fmaf(p, f, 1.0f);
    return p * __int_as_float((n + 127) << 23);
}

__device__ __forceinline__ unsigned long long pk2(float lo, float hi) {
    unsigned long long r;
    asm("mov.b64 %0, {%1,%2};" : "=l"(r) : "f"(lo), "f"(hi));
    return r;
}
__device__ __forceinline__ void upk2(float& lo, float& hi, unsigned long long v) {
    asm("mov.b64 {%0,%1}, %2;" : "=f"(lo), "=f"(hi) : "l"(v));
}
__device__ __forceinline__ unsigned long long ffma2(unsigned long long a,
                                                    unsigned long long b,
                                                    unsigned long long c) {
    unsigned long long d;
    asm("fma.rn.f32x2 %0, %1, %2, %3;" : "=l"(d) : "l"(a), "l"(b), "l"(c));
    return d;
}

__global__ void k_init() {
    int i = blockIdx.x * blockDim.x + threadIdx.x;
    if (i < NROW) {
        g_rmax_enc[i] = 0u; g_cmax_enc[i] = 0u;
        g_rowsum[i] = 0.0f; g_colsum[i] = 0.0f;
    }
}

// attn = q @ k^T (f32x2), fused tile-local row/col max -> global atomicMax
__global__ __launch_bounds__(256, 1)
void k_gemm_qk(const float* __restrict__ q, const float* __restrict__ kmat,
               float* __restrict__ attn)
{
    __shared__ float As[32][132];
    __shared__ float Bs[32][132];
    __shared__ unsigned s_rm[128];
    __shared__ unsigned s_cm[128];

    const int tid = threadIdx.x;
    const int tx = tid & 15, ty = tid >> 4;
    const int b  = blockIdx.z;
    const int m0 = blockIdx.y * 128;
    const int n0 = blockIdx.x * 128;
    const float* qb = q    + (size_t)b * LL * DD;
    const float* kb = kmat + (size_t)b * LL * DD;

    if (tid < 128) { s_rm[tid] = 0u; s_cm[tid] = 0u; }

    unsigned long long acc[8][4];
#pragma unroll
    for (int i = 0; i < 8; i++)
#pragma unroll
        for (int j = 0; j < 4; j++) acc[i][j] = 0ULL;

    for (int kc = 0; kc < DD; kc += 32) {
#pragma unroll
        for (int p = 0; p < 4; p++) {
            int idx = tid + p * 256;
            int r = idx >> 3, c = idx & 7;
            float4 vq = *reinterpret_cast<const float4*>(qb + (size_t)(m0 + r) * DD + kc + 4 * c);
            As[4*c+0][r] = vq.x; As[4*c+1][r] = vq.y; As[4*c+2][r] = vq.z; As[4*c+3][r] = vq.w;
            float4 vk = *reinterpret_cast<const float4*>(kb + (size_t)(n0 + r) * DD + kc + 4 * c);
            Bs[4*c+0][r] = vk.x; Bs[4*c+1][r] = vk.y; Bs[4*c+2][r] = vk.z; Bs[4*c+3][r] = vk.w;
        }
        __syncthreads();
#pragma unroll 8
        for (int s = 0; s < 32; s++) {
            float4 a0 = *reinterpret_cast<const float4*>(&As[s][ty * 8]);
            float4 a1 = *reinterpret_cast<const float4*>(&As[s][ty * 8 + 4]);
            ulonglong2 b0 = *reinterpret_cast<const ulonglong2*>(&Bs[s][tx * 8]);
            ulonglong2 b1 = *reinterpret_cast<const ulonglong2*>(&Bs[s][tx * 8 + 4]);
            unsigned long long ad[8];
            ad[0] = pk2(a0.x, a0.x); ad[1] = pk2(a0.y, a0.y);
            ad[2] = pk2(a0.z, a0.z); ad[3] = pk2(a0.w, a0.w);
            ad[4] = pk2(a1.x, a1.x); ad[5] = pk2(a1.y, a1.y);
            ad[6] = pk2(a1.z, a1.z); ad[7] = pk2(a1.w, a1.w);
#pragma unroll
            for (int i = 0; i < 8; i++) {
                acc[i][0] = ffma2(ad[i], b0.x, acc[i][0]);
                acc[i][1] = ffma2(ad[i], b0.y, acc[i][1]);
                acc[i][2] = ffma2(ad[i], b1.x, acc[i][2]);
                acc[i][3] = ffma2(ad[i], b1.y, acc[i][3]);
            }
        }
        __syncthreads();
    }

    float cm[8];
#pragma unroll
    for (int j = 0; j < 8; j++) cm[j] = -3.4e38f;
#pragma unroll
    for (int i = 0; i < 8; i++) {
        float v0,v1,v2,v3,v4,v5,v6,v7;
        upk2(v0, v1, acc[i][0]); upk2(v2, v3, acc[i][1]);
        upk2(v4, v5, acc[i][2]); upk2(v6, v7, acc[i][3]);
        float rm = fmaxf(fmaxf(fmaxf(v0, v1), fmaxf(v2, v3)),
                         fmaxf(fmaxf(v4, v5), fmaxf(v6, v7)));
        atomicMax(&s_rm[ty * 8 + i], fenc(rm));
        cm[0]=fmaxf(cm[0],v0); cm[1]=fmaxf(cm[1],v1); cm[2]=fmaxf(cm[2],v2); cm[3]=fmaxf(cm[3],v3);
        cm[4]=fmaxf(cm[4],v4); cm[5]=fmaxf(cm[5],v5); cm[6]=fmaxf(cm[6],v6); cm[7]=fmaxf(cm[7],v7);
        float* o = attn + ((size_t)(b * LL + m0 + ty * 8 + i)) * LL + n0 + tx * 8;
        *reinterpret_cast<float4*>(o)     = make_float4(v0, v1, v2, v3);
        *reinterpret_cast<float4*>(o + 4) = make_float4(v4, v5, v6, v7);
    }
#pragma unroll
    for (int j = 0; j < 8; j++) atomicMax(&s_cm[tx * 8 + j], fenc(cm[j]));
    __syncthreads();
    if (tid < 128) {
        atomicMax(&g_rmax_enc[b * LL + m0 + tid], s_rm[tid]);
        atomicMax(&g_cmax_enc[b * LL + n0 + tid], s_cm[tid]);
    }
}

__global__ void k_prep() {
    int i = blockIdx.x * blockDim.x + threadIdx.x;
    if (i < NROW) {
        float rm = fdec(g_rmax_enc[i]);
        g_rmax[i] = rm;
        g_E[i] = fexp(rm);
        g_cfac[i] = fexp(-fdec(g_cmax_enc[i]));  // stage C_j here temporarily
    }
}

// er = exp(a - rmax_i)*m in place; rowsum_i += er; colsum_raw_j += er*E_i
__global__ __launch_bounds__(256)
void k_pass(float* __restrict__ buf, const float* __restrict__ mask)
{
    __shared__ float s_rs[128];
    __shared__ float s_rmax[128];
    __shared__ float s_E[128];
    const int tid = threadIdx.x;
    const int b  = blockIdx.z;
    const int r0 = blockIdx.y * 128;
    const int c0 = blockIdx.x * 128;
    if (tid < 128) {
        s_rs[tid] = 0.0f;
        s_rmax[tid] = g_rmax[b * LL + r0 + tid];
        s_E[tid]    = g_E[b * LL + r0 + tid];
    }
    __syncthreads();
    const int c = tid & 127;
    const int half = tid >> 7;
    const int lane = tid & 31;
    float csum = 0.0f;
    size_t base = ((size_t)(b * LL + r0)) * LL + c0;
    for (int r = half; r < 128; r += 2) {
        size_t idx = base + (size_t)r * LL + c;
        float er = fexp(buf[idx] - s_rmax[r]) * mask[idx];
        buf[idx] = er;
        csum = fmaf(er, s_E[r], csum);
        float w = er;
        w += __shfl_xor_sync(0xffffffffu, w, 16);
        w += __shfl_xor_sync(0xffffffffu, w, 8);
        w += __shfl_xor_sync(0xffffffffu, w, 4);
        w += __shfl_xor_sync(0xffffffffu, w, 2);
        w += __shfl_xor_sync(0xffffffffu, w, 1);
        if (lane == 0) atomicAdd(&s_rs[r], w);
    }
    atomicAdd(&g_colsum[b * LL + c0 + c], csum);
    __syncthreads();
    if (tid < 128) atomicAdd(&g_rowsum[b * LL + r0 + tid], s_rs[tid]);
}

__global__ void k_facts() {
    int i = blockIdx.x * blockDim.x + threadIdx.x;
    if (i < NROW) {
        g_rfac[i] = g_E[i] / (g_rowsum[i] + 1e-12f);
        float C = g_cfac[i];                       // staged C_j
        g_cfac[i] = C / (g_colsum[i] * C + 1e-12f);
    }
}

// gated = er^2 * rfac_i * cfac_j (in place)
__global__ __launch_bounds__(256)
void k_gate(float* __restrict__ buf)
{
    int e4  = blockIdx.x * 256 + threadIdx.x;
    int row = e4 >> 9;
    int b   = row >> 11;
    int col = (e4 & 511) << 2;
    float rf = g_rfac[row];
    float4 cf = *reinterpret_cast<const float4*>(&g_cfac[(b << 11) + col]);
    float4 e = reinterpret_cast<float4*>(buf)[e4];
    e.x = e.x * e.x * rf * cf.x;
    e.y = e.y * e.y * rf * cf.y;
    e.z = e.z * e.z * rf * cf.z;
    e.w = e.w * e.w * rf * cf.w;
    reinterpret_cast<float4*>(buf)[e4] = e;
}

// out = gated @ v (f32x2)
__global__ __launch_bounds__(256, 1)
void k_gemm_pv(const float* __restrict__ gated, const float* __restrict__ v,
               float* __restrict__ out)
{
    __shared__ float Gs[32][132];
    __shared__ float Vs[32][132];
    const int tid = threadIdx.x;
    const int tx = tid & 15, ty = tid >> 4;
    const int b  = blockIdx.y;
    const int m0 = blockIdx.x * 128;
    const float* gb = gated + (size_t)b * LL * LL;
    const float* vb = v     + (size_t)b * LL * DD;

    unsigned long long acc[8][4];
#pragma unroll
    for (int i = 0; i < 8; i++)
#pragma unroll
        for (int j = 0; j < 4; j++) acc[i][j] = 0ULL;

    for (int k0 = 0; k0 < LL; k0 += 32) {
#pragma unroll
        for (int p = 0; p < 4; p++) {
            int idx = tid + p * 256;
            int r = idx >> 3, c = idx & 7;
            float4 vg = *reinterpret_cast<const float4*>(gb + (size_t)(m0 + r) * LL + k0 + 4 * c);
            Gs[4*c+0][r] = vg.x; Gs[4*c+1][r] = vg.y; Gs[4*c+2][r] = vg.z; Gs[4*c+3][r] = vg.w;
            int kr = idx >> 5, cc = idx & 31;
            *reinterpret_cast<float4*>(&Vs[kr][4 * cc]) =
                *reinterpret_cast<const float4*>(vb + (size_t)(k0 + kr) * DD + 4 * cc);
        }
        __syncthreads();
#pragma unroll 8
        for (int s = 0; s < 32; s++) {
            float4 a0 = *reinterpret_cast<const float4*>(&Gs[s][ty * 8]);
            float4 a1 = *reinterpret_cast<const float4*>(&Gs[s][ty * 8 + 4]);
            ulonglong2 b0 = *reinterpret_cast<const ulonglong2*>(&Vs[s][tx * 8]);
            ulonglong2 b1 = *reinterpret_cast<const ulonglong2*>(&Vs[s][tx * 8 + 4]);
            unsigned long long ad[8];
            ad[0] = pk2(a0.x, a0.x); ad[1] = pk2(a0.y, a0.y);
            ad[2] = pk2(a0.z, a0.z); ad[3] = pk2(a0.w, a0.w);
            ad[4] = pk2(a1.x, a1.x); ad[5] = pk2(a1.y, a1.y);
            ad[6] = pk2(a1.z, a1.z); ad[7] = pk2(a1.w, a1.w);
#pragma unroll
            for (int i = 0; i < 8; i++) {
                acc[i][0] = ffma2(ad[i], b0.x, acc[i][0]);
                acc[i][1] = ffma2(ad[i], b0.y, acc[i][1]);
                acc[i][2] = ffma2(ad[i], b1.x, acc[i][2]);
                acc[i][3] = ffma2(ad[i], b1.y, acc[i][3]);
            }
        }
        __syncthreads();
    }
#pragma unroll
    for (int i = 0; i < 8; i++) {
        float v0,v1,v2,v3,v4,v5,v6,v7;
        upk2(v0, v1, acc[i][0]); upk2(v2, v3, acc[i][1]);
        upk2(v4, v5, acc[i][2]); upk2(v6, v7, acc[i][3]);
        float* o = out + ((size_t)(b * LL + m0 + ty * 8 + i)) * DD + tx * 8;
        *reinterpret_cast<float4*>(o)     = make_float4(v0, v1, v2, v3);
        *reinterpret_cast<float4*>(o + 4) = make_float4(v4, v5, v6, v7);
    }
}

extern "C" void kernel_launch(void* const* d_in, const int* in_sizes, int n_in,
                              void* d_out, int out_size)
{
    (void)in_sizes; (void)n_in; (void)out_size;
    const float* q    = (const float*)d_in[0];
    const float* k    = (const float*)d_in[1];
    const float* v    = (const float*)d_in[2];
    const float* mask = (const float*)d_in[3];
    float* out   = (float*)d_out;
    float* gated = out + (size_t)BB * LL * DD;   // scratch = gated output region

    k_init<<<NROW / 256, 256>>>();
    k_gemm_qk<<<dim3(16, 16, 16), 256>>>(q, k, gated);
    k_prep<<<NROW / 256, 256>>>();
    k_pass<<<dim3(16, 16, 16), 256>>>(gated, mask);
    k_facts<<<NROW / 256, 256>>>();
    k_gate<<<(int)(((size_t)BB * LL * LL / 4) / 256), 256>>>(gated);
    k_gemm_pv<<<dim3(16, 16), 256>>>(gated, v, out);
}